// round 1
// baseline (speedup 1.0000x reference)
#include <cuda_runtime.h>
#include <cuda_bf16.h>
#include <math.h>

#define H 128
#define N_IP_MAX 50000
#define N_CON_MAX 200000
#define KB 16

// ---------------- scratch (static __device__ ⇒ no runtime allocation) ----------------
__device__ float g_s0[N_IP_MAX * H];      // ip aggregation buffer
__device__ float g_s1[N_CON_MAX * H];     // con aggregation buffer 1
__device__ float g_s2[N_CON_MAX * H];     // con aggregation buffer 2
__device__ float g_deg0[N_IP_MAX];
__device__ float g_deg1[N_CON_MAX];
__device__ float g_deg2[N_CON_MAX];
__device__ float g_ipA[N_IP_MAX * H];
__device__ float g_ipB[N_IP_MAX * H];
__device__ float g_conA[N_CON_MAX * H];
__device__ float g_conB[N_CON_MAX * H];

// ---------------- scatter-add: one warp per edge ----------------
__global__ void scatter_kernel(const float* __restrict__ x,
                               const int* __restrict__ src,
                               const int* __restrict__ dst,
                               int nE,
                               float* __restrict__ s,
                               float* __restrict__ deg)
{
    int warp = (blockIdx.x * blockDim.x + threadIdx.x) >> 5;
    int lane = threadIdx.x & 31;
    if (warp >= nE) return;
    int si = src[warp];
    int di = dst[warp];
    float4 v = reinterpret_cast<const float4*>(x)[(size_t)si * (H / 4) + lane];
    float* base = s + (size_t)di * H + lane * 4;
    atomicAdd(base + 0, v.x);
    atomicAdd(base + 1, v.y);
    atomicAdd(base + 2, v.z);
    atomicAdd(base + 3, v.w);
    if (lane == 0) atomicAdd(deg + di, 1.0f);
}

// ---------------- fused SAGE combine: GEMM(K=256) + bias + L2norm + optional lrelu --------
// out[r, :] = normalize( (s[r,:]/max(deg,1)) @ Wl + bl + xdst[r,:] @ Wr ) [lrelu]
// Block: 256 threads, tile 128 rows x 128 cols, thread computes 8x8.
template <bool LRELU>
__global__ void __launch_bounds__(256) combine_kernel(
    const float* __restrict__ s, const float* __restrict__ deg,
    const float* __restrict__ xdst,
    const float* __restrict__ Wl, const float* __restrict__ bl,
    const float* __restrict__ Wr,
    float* __restrict__ out, int n)
{
    __shared__ float As[KB][132];   // padded: rows stay 16B-aligned
    __shared__ float Ws[KB][128];
    __shared__ float invd[128];

    int tid  = threadIdx.x;
    int row0 = blockIdx.x * 128;

    if (tid < 128) {
        int r = row0 + tid;
        float d = (r < n) ? deg[r] : 1.0f;
        invd[tid] = 1.0f / fmaxf(d, 1.0f);
    }
    __syncthreads();

    float acc[8][8];
#pragma unroll
    for (int i = 0; i < 8; i++)
#pragma unroll
        for (int j = 0; j < 8; j++) acc[i][j] = 0.0f;

    int trow = tid >> 4;        // 0..15 -> rows trow*8 .. +8
    int tcol = tid & 15;        // 0..15 -> cols tcol*8 .. +8

    // A tile load mapping: each thread loads 8 consecutive k for one row
    int lr  = tid >> 1;          // 0..127
    int lk0 = (tid & 1) * 8;     // 0 or 8
    int grow = row0 + lr;
    bool rowok = grow < n;

    // W tile load mapping
    int wk = tid >> 4;           // 0..15
    int wj = (tid & 15) * 8;     // 0..120

    for (int kt = 0; kt < 2 * H; kt += KB) {
        // ---- load A tile (transposed into smem) ----
        const float* abase;
        float scale;
        if (kt < H) { abase = s    + (size_t)grow * H + kt + lk0;       scale = invd[lr]; }
        else        { abase = xdst + (size_t)grow * H + (kt - H) + lk0; scale = 1.0f;     }
        float4 a0 = make_float4(0.f, 0.f, 0.f, 0.f), a1 = a0;
        if (rowok) {
            a0 = *reinterpret_cast<const float4*>(abase);
            a1 = *reinterpret_cast<const float4*>(abase + 4);
        }
        As[lk0 + 0][lr] = a0.x * scale;
        As[lk0 + 1][lr] = a0.y * scale;
        As[lk0 + 2][lr] = a0.z * scale;
        As[lk0 + 3][lr] = a0.w * scale;
        As[lk0 + 4][lr] = a1.x * scale;
        As[lk0 + 5][lr] = a1.y * scale;
        As[lk0 + 6][lr] = a1.z * scale;
        As[lk0 + 7][lr] = a1.w * scale;

        // ---- load W tile ----
        int gk = kt + wk;
        const float* wbase = (gk < H) ? (Wl + (size_t)gk * H) : (Wr + (size_t)(gk - H) * H);
        float4 w0 = *reinterpret_cast<const float4*>(wbase + wj);
        float4 w1 = *reinterpret_cast<const float4*>(wbase + wj + 4);
        *reinterpret_cast<float4*>(&Ws[wk][wj])     = w0;
        *reinterpret_cast<float4*>(&Ws[wk][wj + 4]) = w1;

        __syncthreads();

#pragma unroll
        for (int k = 0; k < KB; k++) {
            float4 a0v = *reinterpret_cast<const float4*>(&As[k][trow * 8]);
            float4 a1v = *reinterpret_cast<const float4*>(&As[k][trow * 8 + 4]);
            float4 w0v = *reinterpret_cast<const float4*>(&Ws[k][tcol * 8]);
            float4 w1v = *reinterpret_cast<const float4*>(&Ws[k][tcol * 8 + 4]);
            float ar[8] = {a0v.x, a0v.y, a0v.z, a0v.w, a1v.x, a1v.y, a1v.z, a1v.w};
            float wr_[8] = {w0v.x, w0v.y, w0v.z, w0v.w, w1v.x, w1v.y, w1v.z, w1v.w};
#pragma unroll
            for (int i = 0; i < 8; i++)
#pragma unroll
                for (int j = 0; j < 8; j++) acc[i][j] += ar[i] * wr_[j];
        }
        __syncthreads();
    }

    // ---- epilogue: bias + row L2 norm + (lrelu) + store ----
    int col0 = tcol * 8;
    float bias[8];
#pragma unroll
    for (int j = 0; j < 8; j++) bias[j] = bl[col0 + j];

#pragma unroll
    for (int i = 0; i < 8; i++) {
        int r = row0 + trow * 8 + i;
#pragma unroll
        for (int j = 0; j < 8; j++) acc[i][j] += bias[j];
        float ss = 0.0f;
#pragma unroll
        for (int j = 0; j < 8; j++) ss += acc[i][j] * acc[i][j];
        // reduce across the 16 lanes that share this row (same trow group)
#pragma unroll
        for (int off = 8; off >= 1; off >>= 1)
            ss += __shfl_xor_sync(0xffffffffu, ss, off, 16);
        float inv = 1.0f / fmaxf(sqrtf(ss), 1e-12f);
        float4 o0, o1;
        float v[8];
#pragma unroll
        for (int j = 0; j < 8; j++) {
            float t = acc[i][j] * inv;
            if (LRELU) t = (t >= 0.0f) ? t : 0.01f * t;
            v[j] = t;
        }
        o0 = make_float4(v[0], v[1], v[2], v[3]);
        o1 = make_float4(v[4], v[5], v[6], v[7]);
        if (r < n) {
            *reinterpret_cast<float4*>(out + (size_t)r * H + col0)     = o0;
            *reinterpret_cast<float4*>(out + (size_t)r * H + col0 + 4) = o1;
        }
    }
}

// ---------------- elementwise: out = lrelu(a + b) ----------------
__global__ void sum_lrelu_kernel(const float4* __restrict__ a,
                                 const float4* __restrict__ b,
                                 float4* __restrict__ out, int n4)
{
    int i = blockIdx.x * blockDim.x + threadIdx.x;
    if (i >= n4) return;
    float4 x = a[i], y = b[i];
    float4 r;
    r.x = x.x + y.x; r.x = (r.x >= 0.f) ? r.x : 0.01f * r.x;
    r.y = x.y + y.y; r.y = (r.y >= 0.f) ? r.y : 0.01f * r.y;
    r.z = x.z + y.z; r.z = (r.z >= 0.f) ? r.z : 0.01f * r.z;
    r.w = x.w + y.w; r.w = (r.w >= 0.f) ? r.w : 0.01f * r.w;
    out[i] = r;
}

// ---------------- host orchestration ----------------
static inline void run_scatter(const float* x, const int* src, const int* dst, int nE,
                               float* s, float* deg)
{
    int warpsPerBlock = 8;
    int blocks = (nE + warpsPerBlock - 1) / warpsPerBlock;
    scatter_kernel<<<blocks, 256>>>(x, src, dst, nE, s, deg);
}

template <bool LRELU>
static inline void run_combine(const float* s, const float* deg, const float* xdst,
                               const float* Wl, const float* bl, const float* Wr,
                               float* out, int n)
{
    int blocks = (n + 127) / 128;
    combine_kernel<LRELU><<<blocks, 256>>>(s, deg, xdst, Wl, bl, Wr, out, n);
}

extern "C" void kernel_launch(void* const* d_in, const int* in_sizes, int n_in,
                              void* d_out, int out_size)
{
    const float* x_ip  = (const float*)d_in[0];
    const float* x_con = (const float*)d_in[1];
    const int* src_ipcon = (const int*)d_in[2];
    const int* dst_ipcon = (const int*)d_in[3];
    const int* src_conip = (const int*)d_in[4];
    const int* dst_conip = (const int*)d_in[5];
    const int* src_ipip  = (const int*)d_in[6];
    const int* dst_ipip  = (const int*)d_in[7];
    const int* src_csrc  = (const int*)d_in[8];
    const int* dst_csrc  = (const int*)d_in[9];
    const int* src_cdst  = (const int*)d_in[10];
    const int* dst_cdst  = (const int*)d_in[11];
    const float* Wl_t = (const float*)d_in[12];   // [2,3,H,H]
    const float* bl_t = (const float*)d_in[13];   // [2,3,H]
    const float* Wr_t = (const float*)d_in[14];
    const float* Wl_s = (const float*)d_in[15];   // [2,2,H,H]
    const float* bl_s = (const float*)d_in[16];
    const float* Wr_s = (const float*)d_in[17];

    const int n_ip  = in_sizes[0] / H;
    const int n_con = in_sizes[1] / H;
    const int nE_ipcon = in_sizes[2];
    const int nE_conip = in_sizes[4];
    const int nE_ipip  = in_sizes[6];
    const int nE_csrc  = in_sizes[8];
    const int nE_cdst  = in_sizes[10];

    float *s0, *s1, *s2, *deg0, *deg1, *deg2, *ipA, *ipB, *conA, *conB;
    cudaGetSymbolAddress((void**)&s0,   g_s0);
    cudaGetSymbolAddress((void**)&s1,   g_s1);
    cudaGetSymbolAddress((void**)&s2,   g_s2);
    cudaGetSymbolAddress((void**)&deg0, g_deg0);
    cudaGetSymbolAddress((void**)&deg1, g_deg1);
    cudaGetSymbolAddress((void**)&deg2, g_deg2);
    cudaGetSymbolAddress((void**)&ipA,  g_ipA);
    cudaGetSymbolAddress((void**)&ipB,  g_ipB);
    cudaGetSymbolAddress((void**)&conA, g_conA);
    cudaGetSymbolAddress((void**)&conB, g_conB);

    float* out = (float*)d_out;

    for (int l = 0; l < 2; l++) {
        const float* xi = (l == 0) ? x_ip  : ipB;
        const float* xc = (l == 0) ? x_con : conB;

        // ---------- temporal ----------
        cudaMemsetAsync(s0,   0, (size_t)n_ip  * H * sizeof(float), 0);
        cudaMemsetAsync(s1,   0, (size_t)n_con * H * sizeof(float), 0);
        cudaMemsetAsync(s2,   0, (size_t)n_con * H * sizeof(float), 0);
        cudaMemsetAsync(deg0, 0, (size_t)n_ip  * sizeof(float), 0);
        cudaMemsetAsync(deg1, 0, (size_t)n_con * sizeof(float), 0);
        cudaMemsetAsync(deg2, 0, (size_t)n_con * sizeof(float), 0);

        run_scatter(xi, src_ipip, dst_ipip, nE_ipip, s0, deg0);
        run_scatter(xc, src_csrc, dst_csrc, nE_csrc, s1, deg1);
        run_scatter(xc, src_cdst, dst_cdst, nE_cdst, s2, deg2);

        const float* Wl0 = Wl_t + (size_t)(l * 3 + 0) * H * H;
        const float* Wl1 = Wl_t + (size_t)(l * 3 + 1) * H * H;
        const float* Wl2 = Wl_t + (size_t)(l * 3 + 2) * H * H;
        const float* Wr0 = Wr_t + (size_t)(l * 3 + 0) * H * H;
        const float* Wr1 = Wr_t + (size_t)(l * 3 + 1) * H * H;
        const float* Wr2 = Wr_t + (size_t)(l * 3 + 2) * H * H;
        const float* b0  = bl_t + (size_t)(l * 3 + 0) * H;
        const float* b1  = bl_t + (size_t)(l * 3 + 1) * H;
        const float* b2  = bl_t + (size_t)(l * 3 + 2) * H;

        run_combine<true >(s0, deg0, xi, Wl0, b0, Wr0, ipA, n_ip);   // ip temporal (lrelu fused)
        run_combine<false>(s1, deg1, xc, Wl1, b1, Wr1, s1,  n_con);  // con type1 (in-place, norm only)
        run_combine<false>(s2, deg2, xc, Wl2, b2, Wr2, s2,  n_con);  // con type2
        {
            int n4 = n_con * H / 4;
            sum_lrelu_kernel<<<(n4 + 255) / 256, 256>>>(
                (const float4*)s1, (const float4*)s2, (float4*)conA, n4);
        }

        // ---------- spatial ----------
        cudaMemsetAsync(s0,   0, (size_t)n_ip  * H * sizeof(float), 0);
        cudaMemsetAsync(s1,   0, (size_t)n_con * H * sizeof(float), 0);
        cudaMemsetAsync(deg0, 0, (size_t)n_ip  * sizeof(float), 0);
        cudaMemsetAsync(deg1, 0, (size_t)n_con * sizeof(float), 0);

        run_scatter(ipA,  src_ipcon, dst_ipcon, nE_ipcon, s1, deg1);  // ip -> con
        run_scatter(conA, src_conip, dst_conip, nE_conip, s0, deg0);  // con -> ip

        const float* Wls0 = Wl_s + (size_t)(l * 2 + 0) * H * H;  // ip->con
        const float* Wls1 = Wl_s + (size_t)(l * 2 + 1) * H * H;  // con->ip
        const float* Wrs0 = Wr_s + (size_t)(l * 2 + 0) * H * H;
        const float* Wrs1 = Wr_s + (size_t)(l * 2 + 1) * H * H;
        const float* bs0  = bl_s + (size_t)(l * 2 + 0) * H;
        const float* bs1  = bl_s + (size_t)(l * 2 + 1) * H;

        float* out_ip  = (l == 1) ? out : ipB;
        float* out_con = (l == 1) ? (out + (size_t)n_ip * H) : conB;

        run_combine<true>(s1, deg1, conA, Wls0, bs0, Wrs0, out_con, n_con);
        run_combine<true>(s0, deg0, ipA,  Wls1, bs1, Wrs1, out_ip,  n_ip);
    }
}

// round 2
// speedup vs baseline: 1.4496x; 1.4496x over previous
#include <cuda_runtime.h>
#include <cuda_bf16.h>
#include <math.h>
#include <stdint.h>

#define H 128
#define N_IP_MAX 50000
#define N_CON_MAX 200000

// ---------------- scratch (static __device__ => no runtime allocation) ----------------
__device__ float g_s0[N_IP_MAX * H];
__device__ float g_s1[N_CON_MAX * H];
__device__ float g_s2[N_CON_MAX * H];
__device__ float g_deg0[N_IP_MAX];
__device__ float g_deg1[N_CON_MAX];
__device__ float g_deg2[N_CON_MAX];
__device__ float g_ipA[N_IP_MAX * H];
__device__ float g_ipB[N_IP_MAX * H];
__device__ float g_conA[N_CON_MAX * H];
__device__ float g_conB[N_CON_MAX * H];

// ---------------- scatter-add: one warp per edge ----------------
__global__ void scatter_kernel(const float* __restrict__ x,
                               const int* __restrict__ src,
                               const int* __restrict__ dst,
                               int nE,
                               float* __restrict__ s,
                               float* __restrict__ deg)
{
    int warp = (blockIdx.x * blockDim.x + threadIdx.x) >> 5;
    int lane = threadIdx.x & 31;
    if (warp >= nE) return;
    int si = src[warp];
    int di = dst[warp];
    float4 v = reinterpret_cast<const float4*>(x)[(size_t)si * (H / 4) + lane];
    float* base = s + (size_t)di * H + lane * 4;
    atomicAdd(base + 0, v.x);
    atomicAdd(base + 1, v.y);
    atomicAdd(base + 2, v.z);
    atomicAdd(base + 3, v.w);
    if (lane == 0) atomicAdd(deg + di, 1.0f);
}

// ---------------- bf16 split helpers + mma ----------------
__device__ __forceinline__ void split_pack(float x0, float x1, uint32_t& hi, uint32_t& lo)
{
    __nv_bfloat16 h0 = __float2bfloat16(x0);
    __nv_bfloat16 h1 = __float2bfloat16(x1);
    float r0 = x0 - __bfloat162float(h0);
    float r1 = x1 - __bfloat162float(h1);
    __nv_bfloat16 l0 = __float2bfloat16(r0);
    __nv_bfloat16 l1 = __float2bfloat16(r1);
    hi = (uint32_t)__bfloat16_as_ushort(h0) | ((uint32_t)__bfloat16_as_ushort(h1) << 16);
    lo = (uint32_t)__bfloat16_as_ushort(l0) | ((uint32_t)__bfloat16_as_ushort(l1) << 16);
}

__device__ __forceinline__ void mma16816(float* d, const uint32_t* a, uint32_t b0, uint32_t b1)
{
    asm volatile(
        "mma.sync.aligned.m16n8k16.row.col.f32.bf16.bf16.f32 "
        "{%0,%1,%2,%3}, {%4,%5,%6,%7}, {%8,%9}, {%0,%1,%2,%3};"
        : "+f"(d[0]), "+f"(d[1]), "+f"(d[2]), "+f"(d[3])
        : "r"(a[0]), "r"(a[1]), "r"(a[2]), "r"(a[3]), "r"(b0), "r"(b1));
}

// ---------------- fused SAGE combine (tensor-core, 3x-bf16 split) ----------------
// out[r,:] = normalize( (s[r,:]/max(deg,1)) @ Wl + bl + xdst[r,:] @ Wr ) [lrelu]
// Block: 256 threads (8 warps as 2m x 4n), tile 128x128, K=256 in 16 steps of 16.
#define PADA 12    // u32 stride of A-pair rows (8 pairs + pad) -> conflict-free frag loads
#define PADW 136   // u32 stride of W-pair rows (128 + pad)

template <bool LRELU>
__global__ void __launch_bounds__(256) combine_mma_kernel(
    const float* __restrict__ s, const float* __restrict__ deg,
    const float* __restrict__ xdst,
    const float* __restrict__ Wl, const float* __restrict__ bb,
    const float* __restrict__ Wr,
    float* __restrict__ out, int n)
{
    __shared__ uint32_t Ah[2][128 * PADA];
    __shared__ uint32_t Al[2][128 * PADA];
    __shared__ uint32_t Wh[2][8 * PADW];
    __shared__ uint32_t Wlo[2][8 * PADW];
    __shared__ float invd[128];
    __shared__ float ssred[128];

    const int tid  = threadIdx.x;
    const int row0 = blockIdx.x * 128;

    if (tid < 128) {
        int r = row0 + tid;
        invd[tid]  = 1.0f / fmaxf((r < n) ? deg[r] : 1.0f, 1.0f);
        ssred[tid] = 0.0f;
    }
    __syncthreads();

    // ---- pack-stage thread mapping ----
    const int ar   = tid >> 1;            // A row 0..127
    const int ak   = (tid & 1) * 8;       // k offset 0/8
    const int grow = row0 + ar;
    const bool rowok = grow < n;
    const int wk2  = tid >> 5;            // 0..7 (k-pair row)
    const int wn0  = (tid & 31) * 4;      // n offset 0..124

    float af[8];
    float wf0[4], wf1[4];

    auto load_tile = [&](int kt) {
        int k0 = kt * 16;
        const float* ap;
        float sc;
        if (k0 < H) { ap = s    + (size_t)grow * H + k0 + ak;       sc = invd[ar]; }
        else        { ap = xdst + (size_t)grow * H + (k0 - H) + ak; sc = 1.0f;     }
        float4 f0 = make_float4(0.f, 0.f, 0.f, 0.f), f1 = f0;
        if (rowok) {
            f0 = *reinterpret_cast<const float4*>(ap);
            f1 = *reinterpret_cast<const float4*>(ap + 4);
        }
        af[0] = f0.x * sc; af[1] = f0.y * sc; af[2] = f0.z * sc; af[3] = f0.w * sc;
        af[4] = f1.x * sc; af[5] = f1.y * sc; af[6] = f1.z * sc; af[7] = f1.w * sc;

        int gk = k0 + 2 * wk2;
        const float* wb = (gk < H) ? (Wl + (size_t)gk * H) : (Wr + (size_t)(gk - H) * H);
        float4 w0 = *reinterpret_cast<const float4*>(wb + wn0);
        float4 w1 = *reinterpret_cast<const float4*>(wb + H + wn0);
        wf0[0] = w0.x; wf0[1] = w0.y; wf0[2] = w0.z; wf0[3] = w0.w;
        wf1[0] = w1.x; wf1[1] = w1.y; wf1[2] = w1.z; wf1[3] = w1.w;
    };

    auto store_tile = [&](int b) {
        uint32_t hi[4], lo[4];
#pragma unroll
        for (int j = 0; j < 4; j++) split_pack(af[2 * j], af[2 * j + 1], hi[j], lo[j]);
        *reinterpret_cast<uint4*>(&Ah[b][ar * PADA + (ak >> 1)]) = *reinterpret_cast<uint4*>(hi);
        *reinterpret_cast<uint4*>(&Al[b][ar * PADA + (ak >> 1)]) = *reinterpret_cast<uint4*>(lo);
#pragma unroll
        for (int j = 0; j < 4; j++) split_pack(wf0[j], wf1[j], hi[j], lo[j]);
        *reinterpret_cast<uint4*>(&Wh [b][wk2 * PADW + wn0]) = *reinterpret_cast<uint4*>(hi);
        *reinterpret_cast<uint4*>(&Wlo[b][wk2 * PADW + wn0]) = *reinterpret_cast<uint4*>(lo);
    };

    // ---- mma thread mapping ----
    const int lane = tid & 31;
    const int wid  = tid >> 5;
    const int wm   = wid >> 2;  // 0..1 (64-row group)
    const int wn   = wid & 3;   // 0..3 (32-col group)
    const int g    = lane >> 2; // 0..7
    const int c    = lane & 3;  // 0..3

    float acc[4][4][4];
#pragma unroll
    for (int mt = 0; mt < 4; mt++)
#pragma unroll
        for (int nt = 0; nt < 4; nt++)
#pragma unroll
            for (int j = 0; j < 4; j++) acc[mt][nt][j] = 0.0f;

    load_tile(0);
    store_tile(0);
    __syncthreads();

    for (int kt = 0; kt < 16; kt++) {
        int b = kt & 1;
        if (kt + 1 < 16) load_tile(kt + 1);

        uint32_t ahf[4][4], alf[4][4];
#pragma unroll
        for (int mt = 0; mt < 4; mt++) {
            int R  = wm * 64 + mt * 16;
            int i0 = (R + g) * PADA + c;
            int i1 = (R + g + 8) * PADA + c;
            ahf[mt][0] = Ah[b][i0]; ahf[mt][1] = Ah[b][i1];
            ahf[mt][2] = Ah[b][i0 + 4]; ahf[mt][3] = Ah[b][i1 + 4];
            alf[mt][0] = Al[b][i0]; alf[mt][1] = Al[b][i1];
            alf[mt][2] = Al[b][i0 + 4]; alf[mt][3] = Al[b][i1 + 4];
        }
#pragma unroll
        for (int nt = 0; nt < 4; nt++) {
            int col = wn * 32 + nt * 8 + g;
            uint32_t bh0 = Wh [b][c * PADW + col];
            uint32_t bh1 = Wh [b][(c + 4) * PADW + col];
            uint32_t bl0 = Wlo[b][c * PADW + col];
            uint32_t bl1 = Wlo[b][(c + 4) * PADW + col];
#pragma unroll
            for (int mt = 0; mt < 4; mt++) {
                mma16816(acc[mt][nt], ahf[mt], bh0, bh1);  // Ah*Bh
                mma16816(acc[mt][nt], ahf[mt], bl0, bl1);  // Ah*Bl
                mma16816(acc[mt][nt], alf[mt], bh0, bh1);  // Al*Bh
            }
        }
        if (kt + 1 < 16) store_tile((kt + 1) & 1);
        __syncthreads();
    }

    // ---- epilogue: bias + row L2 norm (+lrelu) ----
#pragma unroll
    for (int mt = 0; mt < 4; mt++) {
        float ss0 = 0.0f, ss1 = 0.0f;
#pragma unroll
        for (int nt = 0; nt < 4; nt++) {
            int col = wn * 32 + nt * 8 + c * 2;
            float b0v = bb[col], b1v = bb[col + 1];
            acc[mt][nt][0] += b0v; acc[mt][nt][1] += b1v;
            acc[mt][nt][2] += b0v; acc[mt][nt][3] += b1v;
            ss0 += acc[mt][nt][0] * acc[mt][nt][0] + acc[mt][nt][1] * acc[mt][nt][1];
            ss1 += acc[mt][nt][2] * acc[mt][nt][2] + acc[mt][nt][3] * acc[mt][nt][3];
        }
        ss0 += __shfl_xor_sync(0xffffffffu, ss0, 1);
        ss0 += __shfl_xor_sync(0xffffffffu, ss0, 2);
        ss1 += __shfl_xor_sync(0xffffffffu, ss1, 1);
        ss1 += __shfl_xor_sync(0xffffffffu, ss1, 2);
        if (c == 0) {
            atomicAdd(&ssred[wm * 64 + mt * 16 + g],     ss0);
            atomicAdd(&ssred[wm * 64 + mt * 16 + 8 + g], ss1);
        }
    }
    __syncthreads();

#pragma unroll
    for (int mt = 0; mt < 4; mt++) {
        int rl0 = wm * 64 + mt * 16 + g;
        int rl1 = rl0 + 8;
        float inv0 = 1.0f / fmaxf(sqrtf(ssred[rl0]), 1e-12f);
        float inv1 = 1.0f / fmaxf(sqrtf(ssred[rl1]), 1e-12f);
        int gr0 = row0 + rl0;
        int gr1 = row0 + rl1;
#pragma unroll
        for (int nt = 0; nt < 4; nt++) {
            int col = wn * 32 + nt * 8 + c * 2;
            if (gr0 < n) {
                float v0 = acc[mt][nt][0] * inv0;
                float v1 = acc[mt][nt][1] * inv0;
                if (LRELU) { v0 = (v0 >= 0.f) ? v0 : 0.01f * v0; v1 = (v1 >= 0.f) ? v1 : 0.01f * v1; }
                *reinterpret_cast<float2*>(out + (size_t)gr0 * H + col) = make_float2(v0, v1);
            }
            if (gr1 < n) {
                float v2 = acc[mt][nt][2] * inv1;
                float v3 = acc[mt][nt][3] * inv1;
                if (LRELU) { v2 = (v2 >= 0.f) ? v2 : 0.01f * v2; v3 = (v3 >= 0.f) ? v3 : 0.01f * v3; }
                *reinterpret_cast<float2*>(out + (size_t)gr1 * H + col) = make_float2(v2, v3);
            }
        }
    }
}

// ---------------- elementwise: out = lrelu(a + b) ----------------
__global__ void sum_lrelu_kernel(const float4* __restrict__ a,
                                 const float4* __restrict__ b,
                                 float4* __restrict__ out, int n4)
{
    int i = blockIdx.x * blockDim.x + threadIdx.x;
    if (i >= n4) return;
    float4 x = a[i], y = b[i];
    float4 r;
    r.x = x.x + y.x; r.x = (r.x >= 0.f) ? r.x : 0.01f * r.x;
    r.y = x.y + y.y; r.y = (r.y >= 0.f) ? r.y : 0.01f * r.y;
    r.z = x.z + y.z; r.z = (r.z >= 0.f) ? r.z : 0.01f * r.z;
    r.w = x.w + y.w; r.w = (r.w >= 0.f) ? r.w : 0.01f * r.w;
    out[i] = r;
}

// ---------------- host orchestration ----------------
static inline void run_scatter(const float* x, const int* src, const int* dst, int nE,
                               float* s, float* deg)
{
    int warpsPerBlock = 8;
    int blocks = (nE + warpsPerBlock - 1) / warpsPerBlock;
    scatter_kernel<<<blocks, 256>>>(x, src, dst, nE, s, deg);
}

template <bool LRELU>
static inline void run_combine(const float* s, const float* deg, const float* xdst,
                               const float* Wl, const float* bl, const float* Wr,
                               float* out, int n)
{
    int blocks = (n + 127) / 128;
    combine_mma_kernel<LRELU><<<blocks, 256>>>(s, deg, xdst, Wl, bl, Wr, out, n);
}

extern "C" void kernel_launch(void* const* d_in, const int* in_sizes, int n_in,
                              void* d_out, int out_size)
{
    const float* x_ip  = (const float*)d_in[0];
    const float* x_con = (const float*)d_in[1];
    const int* src_ipcon = (const int*)d_in[2];
    const int* dst_ipcon = (const int*)d_in[3];
    const int* src_conip = (const int*)d_in[4];
    const int* dst_conip = (const int*)d_in[5];
    const int* src_ipip  = (const int*)d_in[6];
    const int* dst_ipip  = (const int*)d_in[7];
    const int* src_csrc  = (const int*)d_in[8];
    const int* dst_csrc  = (const int*)d_in[9];
    const int* src_cdst  = (const int*)d_in[10];
    const int* dst_cdst  = (const int*)d_in[11];
    const float* Wl_t = (const float*)d_in[12];   // [2,3,H,H]
    const float* bl_t = (const float*)d_in[13];   // [2,3,H]
    const float* Wr_t = (const float*)d_in[14];
    const float* Wl_s = (const float*)d_in[15];   // [2,2,H,H]
    const float* bl_s = (const float*)d_in[16];
    const float* Wr_s = (const float*)d_in[17];

    const int n_ip  = in_sizes[0] / H;
    const int n_con = in_sizes[1] / H;
    const int nE_ipcon = in_sizes[2];
    const int nE_conip = in_sizes[4];
    const int nE_ipip  = in_sizes[6];
    const int nE_csrc  = in_sizes[8];
    const int nE_cdst  = in_sizes[10];

    float *s0, *s1, *s2, *deg0, *deg1, *deg2, *ipA, *ipB, *conA, *conB;
    cudaGetSymbolAddress((void**)&s0,   g_s0);
    cudaGetSymbolAddress((void**)&s1,   g_s1);
    cudaGetSymbolAddress((void**)&s2,   g_s2);
    cudaGetSymbolAddress((void**)&deg0, g_deg0);
    cudaGetSymbolAddress((void**)&deg1, g_deg1);
    cudaGetSymbolAddress((void**)&deg2, g_deg2);
    cudaGetSymbolAddress((void**)&ipA,  g_ipA);
    cudaGetSymbolAddress((void**)&ipB,  g_ipB);
    cudaGetSymbolAddress((void**)&conA, g_conA);
    cudaGetSymbolAddress((void**)&conB, g_conB);

    float* out = (float*)d_out;

    for (int l = 0; l < 2; l++) {
        const float* xi = (l == 0) ? x_ip  : ipB;
        const float* xc = (l == 0) ? x_con : conB;

        // ---------- temporal ----------
        cudaMemsetAsync(s0,   0, (size_t)n_ip  * H * sizeof(float), 0);
        cudaMemsetAsync(s1,   0, (size_t)n_con * H * sizeof(float), 0);
        cudaMemsetAsync(s2,   0, (size_t)n_con * H * sizeof(float), 0);
        cudaMemsetAsync(deg0, 0, (size_t)n_ip  * sizeof(float), 0);
        cudaMemsetAsync(deg1, 0, (size_t)n_con * sizeof(float), 0);
        cudaMemsetAsync(deg2, 0, (size_t)n_con * sizeof(float), 0);

        run_scatter(xi, src_ipip, dst_ipip, nE_ipip, s0, deg0);
        run_scatter(xc, src_csrc, dst_csrc, nE_csrc, s1, deg1);
        run_scatter(xc, src_cdst, dst_cdst, nE_cdst, s2, deg2);

        const float* Wl0 = Wl_t + (size_t)(l * 3 + 0) * H * H;
        const float* Wl1 = Wl_t + (size_t)(l * 3 + 1) * H * H;
        const float* Wl2 = Wl_t + (size_t)(l * 3 + 2) * H * H;
        const float* Wr0 = Wr_t + (size_t)(l * 3 + 0) * H * H;
        const float* Wr1 = Wr_t + (size_t)(l * 3 + 1) * H * H;
        const float* Wr2 = Wr_t + (size_t)(l * 3 + 2) * H * H;
        const float* b0  = bl_t + (size_t)(l * 3 + 0) * H;
        const float* b1  = bl_t + (size_t)(l * 3 + 1) * H;
        const float* b2  = bl_t + (size_t)(l * 3 + 2) * H;

        run_combine<true >(s0, deg0, xi, Wl0, b0, Wr0, ipA, n_ip);   // ip temporal (lrelu fused)
        run_combine<false>(s1, deg1, xc, Wl1, b1, Wr1, s1,  n_con);  // con type1 (in-place)
        run_combine<false>(s2, deg2, xc, Wl2, b2, Wr2, s2,  n_con);  // con type2
        {
            int n4 = n_con * H / 4;
            sum_lrelu_kernel<<<(n4 + 255) / 256, 256>>>(
                (const float4*)s1, (const float4*)s2, (float4*)conA, n4);
        }

        // ---------- spatial ----------
        cudaMemsetAsync(s0,   0, (size_t)n_ip  * H * sizeof(float), 0);
        cudaMemsetAsync(s1,   0, (size_t)n_con * H * sizeof(float), 0);
        cudaMemsetAsync(deg0, 0, (size_t)n_ip  * sizeof(float), 0);
        cudaMemsetAsync(deg1, 0, (size_t)n_con * sizeof(float), 0);

        run_scatter(ipA,  src_ipcon, dst_ipcon, nE_ipcon, s1, deg1);  // ip -> con
        run_scatter(conA, src_conip, dst_conip, nE_conip, s0, deg0);  // con -> ip

        const float* Wls0 = Wl_s + (size_t)(l * 2 + 0) * H * H;  // ip->con
        const float* Wls1 = Wl_s + (size_t)(l * 2 + 1) * H * H;  // con->ip
        const float* Wrs0 = Wr_s + (size_t)(l * 2 + 0) * H * H;
        const float* Wrs1 = Wr_s + (size_t)(l * 2 + 1) * H * H;
        const float* bs0  = bl_s + (size_t)(l * 2 + 0) * H;
        const float* bs1  = bl_s + (size_t)(l * 2 + 1) * H;

        float* out_ip  = (l == 1) ? out : ipB;
        float* out_con = (l == 1) ? (out + (size_t)n_ip * H) : conB;

        run_combine<true>(s1, deg1, conA, Wls0, bs0, Wrs0, out_con, n_con);
        run_combine<true>(s0, deg0, ipA,  Wls1, bs1, Wrs1, out_ip,  n_ip);
    }
}